// round 11
// baseline (speedup 1.0000x reference)
#include <cuda_runtime.h>
#include <math_constants.h>
#include <stdint.h>

#define N_ROWS 4096
#define DIM    144
#define KCODES 50257
#define KPADC  50304                 // 393 * 128
#define NT128  393
#define NT64   786
#define NRB    16                    // 4096 / 256 rowblocks
#define ITEMS  (NRB * NT128)         // 6288
#define NBLK   148
#define ZQ_ELEMS (N_ROWS * DIM)

#define GROW   40                    // int8 row: 40 u32 = 160 B (144 data + 16 zero pad)
#define SROW   176                   // smem row stride (bank-conflict-free for ldmatrix)
#define QE_INV 6382639.0f            // 127 * 50257 (exact in fp32)

// smem: A 256x176, B double buffer 128x176 x2, en 128 x2
#define OFF_B    45056
#define BBUF     22528
#define OFF_ENS  90112
#define SMEM_GM  91136

// ---- scratch (device globals; no allocations allowed) ----
__device__ float    g_zn[N_ROWS];
__device__ float    g_qz[N_ROWS];
__device__ float    g_en[KPADC];
__device__ __align__(16) uint32_t g_zq[(size_t)N_ROWS * GROW];
__device__ __align__(16) uint32_t g_eq[(size_t)KPADC * GROW];
__device__ float    g_tmin[(size_t)NT64 * N_ROWS];
__device__ double   g_rowloss[N_ROWS];

// ---------------- helpers ----------------
__device__ __forceinline__ uint32_t smem_u32(const void* p) {
    uint32_t a;
    asm("{ .reg .u64 t; cvta.to.shared.u64 t, %1; cvt.u32.u64 %0, t; }" : "=r"(a) : "l"(p));
    return a;
}

#define CP_ASYNC16(dst, src) \
    asm volatile("cp.async.cg.shared.global [%0], [%1], 16;" :: "r"(dst), "l"(src) : "memory")
#define CP_COMMIT() asm volatile("cp.async.commit_group;" ::: "memory")
#define CP_WAIT1()  asm volatile("cp.async.wait_group 1;" ::: "memory")

#define LDM4(r, addr) \
    asm volatile("ldmatrix.sync.aligned.m8n8.x4.shared.b16 {%0,%1,%2,%3}, [%4];" \
        : "=r"((r)[0]), "=r"((r)[1]), "=r"((r)[2]), "=r"((r)[3]) : "r"(addr))

__device__ __forceinline__ void mma_s8(int* c, const uint32_t* a, const uint32_t* b)
{
    asm volatile(
        "mma.sync.aligned.m16n8k32.row.col.s32.s8.s8.s32 "
        "{%0,%1,%2,%3}, {%4,%5,%6,%7}, {%8,%9}, {%0,%1,%2,%3};\n"
        : "+r"(c[0]), "+r"(c[1]), "+r"(c[2]), "+r"(c[3])
        : "r"(a[0]), "r"(a[1]), "r"(a[2]), "r"(a[3]), "r"(b[0]), "r"(b[1]));
}

__device__ __forceinline__ uint32_t pack4(float x, float y, float z, float w, float inv)
{
    int i0 = __float2int_rn(x * inv);
    int i1 = __float2int_rn(y * inv);
    int i2 = __float2int_rn(z * inv);
    int i3 = __float2int_rn(w * inv);
    return (uint32_t)(i0 & 0xff) | ((uint32_t)(i1 & 0xff) << 8) |
           ((uint32_t)(i2 & 0xff) << 16) | ((uint32_t)(i3 & 0xff) << 24);
}

// ---------------------------------------------------------------------------
// Kernel 1: exact norms (bit-matching NEON order), per-row int8 quantization
// of z (scale rowmax/127), global-scale int8 quantization of emb (|e|<=1/K).
// ---------------------------------------------------------------------------
__global__ void prep_kernel(const float* __restrict__ z,
                            const float* __restrict__ emb)
{
    int gid = blockIdx.x * blockDim.x + threadIdx.x;

    if (gid < N_ROWS) {
        const float4* p = reinterpret_cast<const float4*>(z + (size_t)gid * DIM);
        float p0 = 0.f, p1 = 0.f, p2 = 0.f, p3 = 0.f, mx = 0.f;
        #pragma unroll
        for (int i = 0; i < DIM / 4; ++i) {
            float4 v = p[i];
            p0 = __fmaf_rn(v.x, v.x, p0);
            p1 = __fmaf_rn(v.y, v.y, p1);
            p2 = __fmaf_rn(v.z, v.z, p2);
            p3 = __fmaf_rn(v.w, v.w, p3);
            mx = fmaxf(mx, fmaxf(fmaxf(fabsf(v.x), fabsf(v.y)),
                                 fmaxf(fabsf(v.z), fabsf(v.w))));
        }
        g_zn[gid] = __fadd_rn(__fadd_rn(p0, p1), __fadd_rn(p2, p3));
        mx = fmaxf(mx, 1e-20f);
        g_qz[gid] = mx / 127.f;
        float inv = 127.f / mx;
        uint32_t* dst = g_zq + (size_t)gid * GROW;
        #pragma unroll
        for (int i = 0; i < DIM / 4; ++i) {
            float4 v = p[i];
            dst[i] = pack4(v.x, v.y, v.z, v.w, inv);
        }
        #pragma unroll
        for (int i = 36; i < GROW; ++i) dst[i] = 0;
    }

    if (gid < KPADC) {
        uint32_t* dst = g_eq + (size_t)gid * GROW;
        if (gid < KCODES) {
            const float4* p = reinterpret_cast<const float4*>(emb + (size_t)gid * DIM);
            float p0 = 0.f, p1 = 0.f, p2 = 0.f, p3 = 0.f;
            #pragma unroll
            for (int i = 0; i < DIM / 4; ++i) {
                float4 v = p[i];
                p0 = __fmaf_rn(v.x, v.x, p0);
                p1 = __fmaf_rn(v.y, v.y, p1);
                p2 = __fmaf_rn(v.z, v.z, p2);
                p3 = __fmaf_rn(v.w, v.w, p3);
                dst[i] = pack4(v.x, v.y, v.z, v.w, QE_INV);
            }
            #pragma unroll
            for (int i = 36; i < GROW; ++i) dst[i] = 0;
            g_en[gid] = __fadd_rn(__fadd_rn(p0, p1), __fadd_rn(p2, p3));
        } else {
            #pragma unroll
            for (int i = 0; i < GROW; ++i) dst[i] = 0;
            g_en[gid] = CUDART_INF_F;
        }
    }
}

// ---------------------------------------------------------------------------
// Kernel 2: persistent int8 IMMA GEMM, block tile 256x128, K padded to 160
// (5 x k32 steps). Emits per-(row, 64-code-tile) approx min score.
// ---------------------------------------------------------------------------
__device__ __forceinline__ void prefetch_b(int ct, int buf, int tid,
                                           uint32_t bs_addr, uint32_t ens_addr)
{
    const char* src = reinterpret_cast<const char*>(g_eq) + (size_t)ct * 128 * 160;
    uint32_t dst = bs_addr + buf * BBUF;
    #pragma unroll 5
    for (int i = tid; i < 1280; i += 256) {
        int r = i / 10, ch = i - r * 10;
        CP_ASYNC16(dst + r * SROW + ch * 16, src + r * 160 + ch * 16);
    }
    if (tid < 32)
        CP_ASYNC16(ens_addr + buf * 512 + tid * 16,
                   reinterpret_cast<const char*>(g_en + ct * 128) + tid * 16);
    CP_COMMIT();
}

__global__ void __launch_bounds__(256, 1) gemm_kernel()
{
    extern __shared__ char sm[];
    char* As = sm;

    const int tid  = threadIdx.x;
    const int lane = tid & 31;
    const int wid  = tid >> 5;
    const int wm   = wid >> 1;       // 0..3 : 64-row slab
    const int wn   = wid & 1;        // 0..1 : 64-code half
    const int g    = lane >> 2;
    const int q    = lane & 3;

    const uint32_t sbase    = smem_u32(sm);
    const uint32_t bs_addr  = sbase + OFF_B;
    const uint32_t ens_addr = sbase + OFF_ENS;

    // ldmatrix lane addressing (byte-identical to validated bf16 layout:
    // one k-step = 32 bytes, two 16B halves)
    const int aRow = (lane & 7) + ((lane >> 3) & 1) * 8;
    const int aK16 = (lane >> 4);
    const int bRow = (lane & 7) + (lane >> 4) * 8;
    const int bK16 = (lane >> 3) & 1;

    const uint32_t aBase  = sbase  + (uint32_t)(wm * 64 + aRow) * SROW + aK16 * 16;
    const uint32_t bBase0 = bs_addr + (uint32_t)(wn * 64 + bRow) * SROW + bK16 * 16;

    const int per = ITEMS / NBLK;                 // 42
    const int rem = ITEMS - per * NBLK;           // 72
    int it = blockIdx.x * per + min((int)blockIdx.x, rem);
    const int iend = it + per + (blockIdx.x < rem ? 1 : 0);

    prefetch_b(it % NT128, it & 1, tid, bs_addr, ens_addr);

    int cur_rb = -1;
    float znr[4][2], coefr[4][2];

    for (; it < iend; ++it) {
        const int rb = it / NT128;
        const int ct = it - rb * NT128;

        if (it + 1 < iend) prefetch_b((it + 1) % NT128, (it + 1) & 1, tid, bs_addr, ens_addr);
        else               CP_COMMIT();

        if (rb != cur_rb) {
            cur_rb = rb;
            #pragma unroll 4
            for (int i = tid; i < 2560; i += 256) {
                int r = i / 10, ch = i - r * 10;
                *reinterpret_cast<uint4*>(As + r * SROW + ch * 16) =
                    *reinterpret_cast<const uint4*>(
                        reinterpret_cast<const char*>(g_zq) +
                        (size_t)(rb * 256 + r) * 160 + ch * 16);
            }
            #pragma unroll
            for (int mi = 0; mi < 4; ++mi)
                #pragma unroll
                for (int rh = 0; rh < 2; ++rh) {
                    int r = rb * 256 + wm * 64 + mi * 16 + rh * 8 + g;
                    znr[mi][rh] = g_zn[r];
                    coefr[mi][rh] = -2.0f * __fmul_rn(g_qz[r], 1.0f / QE_INV);
                }
        }

        CP_WAIT1();
        __syncthreads();

        const uint32_t bB = bBase0 + (it & 1) * BBUF;
        const float* eb = reinterpret_cast<const float*>(sm + OFF_ENS) + (it & 1) * 128 + wn * 64;

        int c[4][8][4];
        #pragma unroll
        for (int mi = 0; mi < 4; ++mi)
            #pragma unroll
            for (int ni = 0; ni < 8; ++ni)
                #pragma unroll
                for (int k = 0; k < 4; ++k) c[mi][ni][k] = 0;

        #pragma unroll
        for (int ks = 0; ks < 5; ++ks) {
            uint32_t b[4][4];
            #pragma unroll
            for (int p = 0; p < 4; ++p)
                LDM4(b[p], bB + p * (16 * SROW) + ks * 32);
            #pragma unroll
            for (int mi = 0; mi < 4; ++mi) {
                uint32_t a[4];
                LDM4(a, aBase + mi * (16 * SROW) + ks * 32);
                #pragma unroll
                for (int p = 0; p < 4; ++p) {
                    mma_s8(c[mi][2 * p + 0], a, &b[p][0]);
                    mma_s8(c[mi][2 * p + 1], a, &b[p][2]);
                }
            }
        }

        // Epilogue: score = fma((float)isum, -2*qz*qe, zn+en); per-row tile min.
        float vmin[4][2];
        #pragma unroll
        for (int mi = 0; mi < 4; ++mi) { vmin[mi][0] = CUDART_INF_F; vmin[mi][1] = CUDART_INF_F; }

        #pragma unroll
        for (int ni = 0; ni < 8; ++ni) {
            const int noff = (ni >> 1) * 16 + (ni & 1) * 8;
            float2 e = *reinterpret_cast<const float2*>(eb + noff + q * 2);
            #pragma unroll
            for (int mi = 0; mi < 4; ++mi) {
                vmin[mi][0] = fminf(vmin[mi][0],
                    __fmaf_rn((float)c[mi][ni][0], coefr[mi][0], znr[mi][0] + e.x));
                vmin[mi][0] = fminf(vmin[mi][0],
                    __fmaf_rn((float)c[mi][ni][1], coefr[mi][0], znr[mi][0] + e.y));
                vmin[mi][1] = fminf(vmin[mi][1],
                    __fmaf_rn((float)c[mi][ni][2], coefr[mi][1], znr[mi][1] + e.x));
                vmin[mi][1] = fminf(vmin[mi][1],
                    __fmaf_rn((float)c[mi][ni][3], coefr[mi][1], znr[mi][1] + e.y));
            }
        }
        #pragma unroll
        for (int mi = 0; mi < 4; ++mi)
            #pragma unroll
            for (int rh = 0; rh < 2; ++rh) {
                float v = vmin[mi][rh];
                v = fminf(v, __shfl_xor_sync(0xffffffffu, v, 1));
                v = fminf(v, __shfl_xor_sync(0xffffffffu, v, 2));
                vmin[mi][rh] = v;
            }
        if (q == 0) {
            const size_t base = (size_t)(2 * ct + wn) * N_ROWS + rb * 256 + wm * 64;
            #pragma unroll
            for (int mi = 0; mi < 4; ++mi)
                #pragma unroll
                for (int rh = 0; rh < 2; ++rh)
                    g_tmin[base + mi * 16 + rh * 8 + g] = vmin[mi][rh];
        }
        __syncthreads();
    }
}

// ---------------------------------------------------------------------------
// Kernel 3: per-row exact rescore with DATA-DRIVEN margin covering the
// guaranteed int8 quantization error:
//   2(||dz||*||e|| + ||z||*||de||) <= qz*2.8652e-3 + sqrt(zn)*1.8802e-6,
// plus 8e-5 fp32-evaluation slack. Exact scoring bit-matches reference.
// ---------------------------------------------------------------------------
__global__ void __launch_bounds__(128) rescore_kernel(const float* __restrict__ z,
                                                      const float* __restrict__ emb,
                                                      float* __restrict__ out)
{
    __shared__ float  zs[DIM];
    __shared__ float  smin[128];
    __shared__ int    list[NT64];
    __shared__ int    cnt;
    __shared__ float  stage[64 * 145];
    __shared__ float  rbv[128];
    __shared__ int    rbi[128];
    __shared__ double dred[128];

    const int row = blockIdx.x;
    const int tid = threadIdx.x;

    float tv[7]; int ti[7]; int nl = 0;
    float mloc = CUDART_INF_F;
    for (int i = tid; i < NT64; i += 128) {
        float v = g_tmin[(size_t)i * N_ROWS + row];
        tv[nl] = v; ti[nl] = i; ++nl;
        mloc = fminf(mloc, v);
    }
    for (int i = tid; i < DIM; i += 128) zs[i] = z[(size_t)row * DIM + i];
    if (tid == 0) cnt = 0;
    smin[tid] = mloc;
    __syncthreads();
    for (int s = 64; s > 0; s >>= 1) {
        if (tid < s) smin[tid] = fminf(smin[tid], smin[tid + s]);
        __syncthreads();
    }
    const float zn = g_zn[row];
    const float qz = g_qz[row];
    const float margin = qz * 2.8652e-3f + sqrtf(zn) * 1.8802e-6f + 8e-5f;
    const float tau = smin[0] + margin;
    for (int u = 0; u < nl; ++u)
        if (tv[u] <= tau) list[atomicAdd(&cnt, 1)] = ti[u];
    __syncthreads();
    const int nc = cnt;

    float bv = CUDART_INF_F;
    int   bi = 0x7fffffff;
    for (int li = 0; li < nc; ++li) {
        const int t64 = list[li];
        const int cb = t64 * 64;
        for (int idx = tid; idx < 64 * DIM; idx += 128) {
            int r = idx / DIM;
            int col = idx - r * DIM;
            int code = cb + r;
            stage[r * 145 + col] = (code < KCODES) ? emb[(size_t)code * DIM + col] : 0.f;
        }
        __syncthreads();
        if (tid < 64) {
            int code = cb + tid;
            if (code < KCODES) {
                float acc = 0.f;
                const float* es = &stage[tid * 145];
                #pragma unroll 8
                for (int d = 0; d < DIM; ++d)
                    acc = __fmaf_rn(zs[d], es[d], acc);
                float t1 = __fadd_rn(zn, g_en[code]);
                float dd = __fmaf_rn(acc, -2.f, t1);
                if (dd < bv || (dd == bv && code < bi)) { bv = dd; bi = code; }
            }
        }
        __syncthreads();
    }

    rbv[tid] = bv; rbi[tid] = bi;
    __syncthreads();
    for (int s = 64; s > 0; s >>= 1) {
        if (tid < s) {
            float v2 = rbv[tid + s]; int b2 = rbi[tid + s];
            if (v2 < rbv[tid] || (v2 == rbv[tid] && b2 < rbi[tid])) {
                rbv[tid] = v2; rbi[tid] = b2;
            }
        }
        __syncthreads();
    }
    const int wbi = rbi[0];
    if (tid == 0) out[ZQ_ELEMS + row] = (float)wbi;

    double ls = 0.0;
    for (int i = tid; i < DIM; i += 128) {
        float e = emb[(size_t)wbi * DIM + i];
        out[(size_t)row * DIM + i] = e;
        float dx = e - zs[i];
        ls += (double)dx * dx;
    }
    dred[tid] = ls;
    __syncthreads();
    for (int s = 64; s > 0; s >>= 1) {
        if (tid < s) dred[tid] += dred[tid + s];
        __syncthreads();
    }
    if (tid == 0) g_rowloss[row] = dred[0];
}

// Kernel 4: deterministic loss reduction (1024 threads).
__global__ void loss_kernel(float* __restrict__ out)
{
    __shared__ double dred[1024];
    int tid = threadIdx.x;
    double s = 0.0;
    for (int i = tid; i < N_ROWS; i += 1024) s += g_rowloss[i];
    dred[tid] = s;
    __syncthreads();
    for (int st = 512; st > 0; st >>= 1) {
        if (tid < st) dred[tid] += dred[tid + st];
        __syncthreads();
    }
    if (tid == 0) out[ZQ_ELEMS + N_ROWS] = (float)(dred[0] / (double)ZQ_ELEMS);
}

// ---------------------------------------------------------------------------
extern "C" void kernel_launch(void* const* d_in, const int* in_sizes, int n_in,
                              void* d_out, int out_size)
{
    const float* z = nullptr;
    const float* emb = nullptr;
    for (int i = 0; i < n_in; ++i) {
        if (in_sizes[i] == N_ROWS * DIM)      z = (const float*)d_in[i];
        else if (in_sizes[i] == KCODES * DIM) emb = (const float*)d_in[i];
    }
    float* out = (float*)d_out;
    (void)out_size;

    cudaFuncSetAttribute(gemm_kernel,
                         cudaFuncAttributeMaxDynamicSharedMemorySize, SMEM_GM);

    prep_kernel<<<(KPADC + 255) / 256, 256>>>(z, emb);
    gemm_kernel<<<NBLK, 256, SMEM_GM>>>();
    rescore_kernel<<<N_ROWS, 128>>>(z, emb, out);
    loss_kernel<<<1, 1024>>>(out);
}

// round 12
// speedup vs baseline: 2.5433x; 2.5433x over previous
#include <cuda_runtime.h>
#include <cuda_fp16.h>
#include <math_constants.h>
#include <stdint.h>

#define N_ROWS 4096
#define DIM    144
#define KCODES 50257
#define KPADC  50304                 // 393 * 128
#define KP     152                   // padded f16 row width (304 bytes)
#define NT128  393
#define NT64   786
#define NRB    16                    // 4096 / 256 rowblocks
#define ITEMS  (NRB * NT128)         // 6288
#define NBLK   148
#define ZQ_ELEMS (N_ROWS * DIM)

#define ESCALE   16384.0f            // 2^14, exact
#define DCOEF    (-1.220703125e-4f)  // -2 * 2^-14, exact

// smem: A 256x304, B double buffer 128x304 x2, en 128 x2
#define OFF_B    77824
#define BBUF     38912
#define OFF_ENS  155648
#define SMEM_GM  156672

// ---- scratch (device globals; no allocations allowed) ----
__device__ float   g_zn[N_ROWS];
__device__ float   g_en[KPADC];
__device__ __half  g_zh[(size_t)N_ROWS * KP];
__device__ __half  g_eh[(size_t)KPADC * KP];
__device__ float   g_tmin[(size_t)NT64 * N_ROWS];
__device__ double  g_rowloss[N_ROWS];

// ---------------- helpers ----------------
__device__ __forceinline__ uint32_t smem_u32(const void* p) {
    uint32_t a;
    asm("{ .reg .u64 t; cvta.to.shared.u64 t, %1; cvt.u32.u64 %0, t; }" : "=r"(a) : "l"(p));
    return a;
}

#define CP_ASYNC16(dst, src) \
    asm volatile("cp.async.cg.shared.global [%0], [%1], 16;" :: "r"(dst), "l"(src) : "memory")
#define CP_COMMIT() asm volatile("cp.async.commit_group;" ::: "memory")
#define CP_WAIT1()  asm volatile("cp.async.wait_group 1;" ::: "memory")

#define LDM4(r, addr) \
    asm volatile("ldmatrix.sync.aligned.m8n8.x4.shared.b16 {%0,%1,%2,%3}, [%4];" \
        : "=r"((r)[0]), "=r"((r)[1]), "=r"((r)[2]), "=r"((r)[3]) : "r"(addr))

// f16 inputs, f16 accumulators: D/C are 2 regs (4 packed halves)
__device__ __forceinline__ void mma_f16(uint32_t* c, const uint32_t* a, const uint32_t* b)
{
    asm volatile(
        "mma.sync.aligned.m16n8k16.row.col.f16.f16.f16.f16 "
        "{%0,%1}, {%2,%3,%4,%5}, {%6,%7}, {%0,%1};\n"
        : "+r"(c[0]), "+r"(c[1])
        : "r"(a[0]), "r"(a[1]), "r"(a[2]), "r"(a[3]), "r"(b[0]), "r"(b[1]));
}

// ---------------------------------------------------------------------------
// Kernel 1: exact norms (bit-matching NEON order) + fp16 copies.
// z stored as-is (O(1), fp16 normal); e scaled by 2^14 (all normal fp16).
// ---------------------------------------------------------------------------
__global__ void prep_kernel(const float* __restrict__ z,
                            const float* __restrict__ emb)
{
    int gid = blockIdx.x * blockDim.x + threadIdx.x;
    __half2 zero2 = __floats2half2_rn(0.f, 0.f);

    if (gid < N_ROWS) {
        const float4* p = reinterpret_cast<const float4*>(z + (size_t)gid * DIM);
        __half2* dst = reinterpret_cast<__half2*>(g_zh + (size_t)gid * KP);
        float p0 = 0.f, p1 = 0.f, p2 = 0.f, p3 = 0.f;
        #pragma unroll
        for (int i = 0; i < DIM / 4; ++i) {
            float4 v = p[i];
            p0 = __fmaf_rn(v.x, v.x, p0);
            p1 = __fmaf_rn(v.y, v.y, p1);
            p2 = __fmaf_rn(v.z, v.z, p2);
            p3 = __fmaf_rn(v.w, v.w, p3);
            dst[i * 2 + 0] = __floats2half2_rn(v.x, v.y);
            dst[i * 2 + 1] = __floats2half2_rn(v.z, v.w);
        }
        #pragma unroll
        for (int i = 72; i < KP / 2; ++i) dst[i] = zero2;
        g_zn[gid] = __fadd_rn(__fadd_rn(p0, p1), __fadd_rn(p2, p3));
    }

    if (gid < KPADC) {
        __half2* dst = reinterpret_cast<__half2*>(g_eh + (size_t)gid * KP);
        if (gid < KCODES) {
            const float4* p = reinterpret_cast<const float4*>(emb + (size_t)gid * DIM);
            float p0 = 0.f, p1 = 0.f, p2 = 0.f, p3 = 0.f;
            #pragma unroll
            for (int i = 0; i < DIM / 4; ++i) {
                float4 v = p[i];
                p0 = __fmaf_rn(v.x, v.x, p0);
                p1 = __fmaf_rn(v.y, v.y, p1);
                p2 = __fmaf_rn(v.z, v.z, p2);
                p3 = __fmaf_rn(v.w, v.w, p3);
                dst[i * 2 + 0] = __floats2half2_rn(v.x * ESCALE, v.y * ESCALE);
                dst[i * 2 + 1] = __floats2half2_rn(v.z * ESCALE, v.w * ESCALE);
            }
            #pragma unroll
            for (int i = 72; i < KP / 2; ++i) dst[i] = zero2;
            g_en[gid] = __fadd_rn(__fadd_rn(p0, p1), __fadd_rn(p2, p3));
        } else {
            for (int i = 0; i < KP / 2; ++i) dst[i] = zero2;
            g_en[gid] = CUDART_INF_F;
        }
    }
}

// ---------------------------------------------------------------------------
// Kernel 2: persistent f16 mma.sync GEMM (f16 accumulators), tile 256x128,
// ldmatrix + cp.async double-buffered B. Per-(row, 64-code-tile) approx min.
// ---------------------------------------------------------------------------
__device__ __forceinline__ void prefetch_b(int ct, int buf, int tid,
                                           uint32_t bs_addr, uint32_t ens_addr)
{
    const char* src = reinterpret_cast<const char*>(g_eh) + (size_t)ct * 128 * 304;
    uint32_t dst = bs_addr + buf * BBUF;
    #pragma unroll 5
    for (int i = tid; i < 2432; i += 256)
        CP_ASYNC16(dst + i * 16, src + (size_t)i * 16);
    if (tid < 32)
        CP_ASYNC16(ens_addr + buf * 512 + tid * 16,
                   reinterpret_cast<const char*>(g_en + ct * 128) + tid * 16);
    CP_COMMIT();
}

__global__ void __launch_bounds__(256, 1) gemm_kernel()
{
    extern __shared__ char sm[];
    char* As = sm;

    const int tid  = threadIdx.x;
    const int lane = tid & 31;
    const int wid  = tid >> 5;
    const int wm   = wid >> 1;       // 0..3 : 64-row slab
    const int wn   = wid & 1;        // 0..1 : 64-code half
    const int g    = lane >> 2;
    const int q    = lane & 3;

    const uint32_t sbase    = smem_u32(sm);
    const uint32_t bs_addr  = sbase + OFF_B;
    const uint32_t ens_addr = sbase + OFF_ENS;

    // ldmatrix lane addressing (validated fragment layout; b16 elements)
    const int aRow = (lane & 7) + ((lane >> 3) & 1) * 8;
    const int aK16 = (lane >> 4);
    const int bRow = (lane & 7) + (lane >> 4) * 8;
    const int bK16 = (lane >> 3) & 1;

    const uint32_t aBase  = sbase   + (uint32_t)(wm * 64 + aRow) * 304 + aK16 * 16;
    const uint32_t bBase0 = bs_addr + (uint32_t)(wn * 64 + bRow) * 304 + bK16 * 16;

    const int per = ITEMS / NBLK;                 // 42
    const int rem = ITEMS - per * NBLK;           // 72
    int it = blockIdx.x * per + min((int)blockIdx.x, rem);
    const int iend = it + per + (blockIdx.x < rem ? 1 : 0);

    prefetch_b(it % NT128, it & 1, tid, bs_addr, ens_addr);

    int cur_rb = -1;
    float znr[4][2];

    for (; it < iend; ++it) {
        const int rb = it / NT128;
        const int ct = it - rb * NT128;

        if (it + 1 < iend) prefetch_b((it + 1) % NT128, (it + 1) & 1, tid, bs_addr, ens_addr);
        else               CP_COMMIT();

        if (rb != cur_rb) {
            cur_rb = rb;
            const uint4* src = reinterpret_cast<const uint4*>(g_zh + (size_t)rb * 256 * KP);
            uint4* dst = reinterpret_cast<uint4*>(As);
            #pragma unroll 4
            for (int i = tid; i < 4864; i += 256) dst[i] = src[i];
            #pragma unroll
            for (int mi = 0; mi < 4; ++mi)
                #pragma unroll
                for (int rh = 0; rh < 2; ++rh)
                    znr[mi][rh] = g_zn[rb * 256 + wm * 64 + mi * 16 + rh * 8 + g];
        }

        CP_WAIT1();
        __syncthreads();

        const uint32_t bB = bBase0 + (it & 1) * BBUF;
        const float* eb = reinterpret_cast<const float*>(sm + OFF_ENS) + (it & 1) * 128 + wn * 64;

        uint32_t c[4][8][2];
        #pragma unroll
        for (int mi = 0; mi < 4; ++mi)
            #pragma unroll
            for (int ni = 0; ni < 8; ++ni) { c[mi][ni][0] = 0u; c[mi][ni][1] = 0u; }

        #pragma unroll
        for (int ks = 0; ks < 9; ++ks) {
            uint32_t b[4][4];
            #pragma unroll
            for (int p = 0; p < 4; ++p)
                LDM4(b[p], bB + p * (16 * 304) + ks * 32);
            #pragma unroll
            for (int mi = 0; mi < 4; ++mi) {
                uint32_t a[4];
                LDM4(a, aBase + mi * (16 * 304) + ks * 32);
                #pragma unroll
                for (int p = 0; p < 4; ++p) {
                    mma_f16(c[mi][2 * p + 0], a, &b[p][0]);   // n offset p*16
                    mma_f16(c[mi][2 * p + 1], a, &b[p][2]);   // n offset p*16+8
                }
            }
        }

        // Epilogue: d = fma(dot_s, -2*2^-14, zn+en); per-row min over 128 codes.
        float vmin[4][2];
        #pragma unroll
        for (int mi = 0; mi < 4; ++mi) { vmin[mi][0] = CUDART_INF_F; vmin[mi][1] = CUDART_INF_F; }

        #pragma unroll
        for (int ni = 0; ni < 8; ++ni) {
            const int noff = (ni >> 1) * 16 + (ni & 1) * 8;    // mma n mapping
            float2 e = *reinterpret_cast<const float2*>(eb + noff + q * 2);
            #pragma unroll
            for (int mi = 0; mi < 4; ++mi) {
                float2 lo = __half22float2(*reinterpret_cast<const __half2*>(&c[mi][ni][0]));
                float2 hi = __half22float2(*reinterpret_cast<const __half2*>(&c[mi][ni][1]));
                vmin[mi][0] = fminf(vmin[mi][0], __fmaf_rn(lo.x, DCOEF, znr[mi][0] + e.x));
                vmin[mi][0] = fminf(vmin[mi][0], __fmaf_rn(lo.y, DCOEF, znr[mi][0] + e.y));
                vmin[mi][1] = fminf(vmin[mi][1], __fmaf_rn(hi.x, DCOEF, znr[mi][1] + e.x));
                vmin[mi][1] = fminf(vmin[mi][1], __fmaf_rn(hi.y, DCOEF, znr[mi][1] + e.y));
            }
        }
        #pragma unroll
        for (int mi = 0; mi < 4; ++mi)
            #pragma unroll
            for (int rh = 0; rh < 2; ++rh) {
                float v = vmin[mi][rh];
                v = fminf(v, __shfl_xor_sync(0xffffffffu, v, 1));
                v = fminf(v, __shfl_xor_sync(0xffffffffu, v, 2));
                vmin[mi][rh] = v;
            }
        if (q == 0) {
            const size_t base = (size_t)(2 * ct + wn) * N_ROWS + rb * 256 + wm * 64;
            #pragma unroll
            for (int mi = 0; mi < 4; ++mi)
                #pragma unroll
                for (int rh = 0; rh < 2; ++rh)
                    g_tmin[base + mi * 16 + rh * 8 + g] = vmin[mi][rh];
        }
        __syncthreads();
    }
}

// ---------------------------------------------------------------------------
// Kernel 3: per-row exact rescore. Margin covers the rigorous fp16 filter
// error bound: 2(||dz||*||e|| + ||z||*||de|| + accum) <= 4e-6*sqrt(zn),
// plus fp32-eval slack 4e-5. Exact scoring bit-matches reference.
// ---------------------------------------------------------------------------
__global__ void __launch_bounds__(128) rescore_kernel(const float* __restrict__ z,
                                                      const float* __restrict__ emb,
                                                      float* __restrict__ out)
{
    __shared__ float  zs[DIM];
    __shared__ float  smin[128];
    __shared__ int    list[NT64];
    __shared__ int    cnt;
    __shared__ float  stage[64 * 145];
    __shared__ float  rbv[128];
    __shared__ int    rbi[128];
    __shared__ double dred[128];

    const int row = blockIdx.x;
    const int tid = threadIdx.x;

    float tv[7]; int ti[7]; int nl = 0;
    float mloc = CUDART_INF_F;
    for (int i = tid; i < NT64; i += 128) {
        float v = g_tmin[(size_t)i * N_ROWS + row];
        tv[nl] = v; ti[nl] = i; ++nl;
        mloc = fminf(mloc, v);
    }
    for (int i = tid; i < DIM; i += 128) zs[i] = z[(size_t)row * DIM + i];
    if (tid == 0) cnt = 0;
    smin[tid] = mloc;
    __syncthreads();
    for (int s = 64; s > 0; s >>= 1) {
        if (tid < s) smin[tid] = fminf(smin[tid], smin[tid + s]);
        __syncthreads();
    }
    const float zn = g_zn[row];
    const float margin = 4e-5f + 4e-6f * sqrtf(zn);
    const float tau = smin[0] + margin;
    for (int u = 0; u < nl; ++u)
        if (tv[u] <= tau) list[atomicAdd(&cnt, 1)] = ti[u];
    __syncthreads();
    const int nc = cnt;

    float bv = CUDART_INF_F;
    int   bi = 0x7fffffff;
    for (int li = 0; li < nc; ++li) {
        const int t64 = list[li];
        const int cb = t64 * 64;
        for (int idx = tid; idx < 64 * DIM; idx += 128) {
            int r = idx / DIM;
            int col = idx - r * DIM;
            int code = cb + r;
            stage[r * 145 + col] = (code < KCODES) ? emb[(size_t)code * DIM + col] : 0.f;
        }
        __syncthreads();
        if (tid < 64) {
            int code = cb + tid;
            if (code < KCODES) {
                float acc = 0.f;
                const float* es = &stage[tid * 145];
                #pragma unroll 8
                for (int d = 0; d < DIM; ++d)
                    acc = __fmaf_rn(zs[d], es[d], acc);
                float t1 = __fadd_rn(zn, g_en[code]);
                float dd = __fmaf_rn(acc, -2.f, t1);
                if (dd < bv || (dd == bv && code < bi)) { bv = dd; bi = code; }
            }
        }
        __syncthreads();
    }

    rbv[tid] = bv; rbi[tid] = bi;
    __syncthreads();
    for (int s = 64; s > 0; s >>= 1) {
        if (tid < s) {
            float v2 = rbv[tid + s]; int b2 = rbi[tid + s];
            if (v2 < rbv[tid] || (v2 == rbv[tid] && b2 < rbi[tid])) {
                rbv[tid] = v2; rbi[tid] = b2;
            }
        }
        __syncthreads();
    }
    const int wbi = rbi[0];
    if (tid == 0) out[ZQ_ELEMS + row] = (float)wbi;

    double ls = 0.0;
    for (int i = tid; i < DIM; i += 128) {
        float e = emb[(size_t)wbi * DIM + i];
        out[(size_t)row * DIM + i] = e;
        float dx = e - zs[i];
        ls += (double)dx * dx;
    }
    dred[tid] = ls;
    __syncthreads();
    for (int s = 64; s > 0; s >>= 1) {
        if (tid < s) dred[tid] += dred[tid + s];
        __syncthreads();
    }
    if (tid == 0) g_rowloss[row] = dred[0];
}

// Kernel 4: deterministic loss reduction.
__global__ void loss_kernel(float* __restrict__ out)
{
    __shared__ double dred[1024];
    int tid = threadIdx.x;
    double s = 0.0;
    for (int i = tid; i < N_ROWS; i += 1024) s += g_rowloss[i];
    dred[tid] = s;
    __syncthreads();
    for (int st = 512; st > 0; st >>= 1) {
        if (tid < st) dred[tid] += dred[tid + st];
        __syncthreads();
    }
    if (tid == 0) out[ZQ_ELEMS + N_ROWS] = (float)(dred[0] / (double)ZQ_ELEMS);
}

// ---------------------------------------------------------------------------
extern "C" void kernel_launch(void* const* d_in, const int* in_sizes, int n_in,
                              void* d_out, int out_size)
{
    const float* z = nullptr;
    const float* emb = nullptr;
    for (int i = 0; i < n_in; ++i) {
        if (in_sizes[i] == N_ROWS * DIM)      z = (const float*)d_in[i];
        else if (in_sizes[i] == KCODES * DIM) emb = (const float*)d_in[i];
    }
    float* out = (float*)d_out;
    (void)out_size;

    cudaFuncSetAttribute(gemm_kernel,
                         cudaFuncAttributeMaxDynamicSharedMemorySize, SMEM_GM);

    prep_kernel<<<(KPADC + 255) / 256, 256>>>(z, emb);
    gemm_kernel<<<NBLK, 256, SMEM_GM>>>();
    rescore_kernel<<<N_ROWS, 128>>>(z, emb, out);
    loss_kernel<<<1, 1024>>>(out);
}